// round 2
// baseline (speedup 1.0000x reference)
#include <cuda_runtime.h>
#include <cuda_bf16.h>

// Scratch (allocation-free rule: __device__ globals)
__device__ float g_ss[256];            // per-column scale/shift for BN
__device__ float g_xn[8192 * 128];     // normalized state
__device__ float g_y [8192 * 256];     // X@W buffers
__device__ float g_h [8192 * 256];     // relu(A@Y + b)
__device__ float g_z [8192 * 128];     // relu(h@Wq1 + bq1)

// ---------------- f32x2 packed helpers ----------------
__device__ __forceinline__ unsigned long long pack2(float lo, float hi) {
    unsigned long long r;
    asm("mov.b64 %0, {%1, %2};" : "=l"(r) : "f"(lo), "f"(hi));
    return r;
}
__device__ __forceinline__ void unpack2(unsigned long long v, float& lo, float& hi) {
    asm("mov.b64 {%0, %1}, %2;" : "=f"(lo), "=f"(hi) : "l"(v));
}
__device__ __forceinline__ unsigned long long ffma2(unsigned long long a,
                                                    unsigned long long b,
                                                    unsigned long long c) {
    unsigned long long d;
    asm("fma.rn.f32x2 %0, %1, %2, %3;" : "=l"(d) : "l"(a), "l"(b), "l"(c));
    return d;
}

// ---------------- BatchNorm ----------------
// One block per column (d0=128). Computes scale = gamma*rstd, shift = beta - mean*scale.
__global__ void bn_stats_kernel(const float* __restrict__ state,
                                const float* __restrict__ gamma,
                                const float* __restrict__ beta,
                                float* __restrict__ ss) {
    const int j = blockIdx.x;      // column
    float s = 0.f, s2 = 0.f;
    for (int i = threadIdx.x; i < 8192; i += 256) {
        float v = state[i * 128 + j];
        s += v; s2 += v * v;
    }
    __shared__ float sh[512];
    sh[threadIdx.x] = s;
    sh[256 + threadIdx.x] = s2;
    __syncthreads();
    for (int o = 128; o > 0; o >>= 1) {
        if (threadIdx.x < o) {
            sh[threadIdx.x] += sh[threadIdx.x + o];
            sh[256 + threadIdx.x] += sh[256 + threadIdx.x + o];
        }
        __syncthreads();
    }
    if (threadIdx.x == 0) {
        float mean = sh[0] * (1.f / 8192.f);
        float var  = sh[256] * (1.f / 8192.f) - mean * mean;
        float rstd = rsqrtf(var + 1e-5f);
        float sc = gamma[j] * rstd;
        ss[j]       = sc;
        ss[128 + j] = beta[j] - mean * sc;
    }
}

__global__ void bn_apply_kernel(const float* __restrict__ state,
                                const float* __restrict__ ss,
                                float* __restrict__ xn) {
    int idx = blockIdx.x * blockDim.x + threadIdx.x;
    if (idx < 8192 * 128) {
        int j = idx & 127;
        xn[idx] = fmaf(state[idx], ss[j], ss[128 + j]);
    }
}

// ---------------- SGEMM: C[M,N] = op(A[M,K] @ B[K,N] + bias) ----------------
// BM=128, BN=64, BK=8, TM=8, TN=4, 256 threads. f32x2 packed FMA, pairs along M.
// Requires M%128==0, N%64==0, K%8==0 (true for all call sites here).
template <bool BIAS, bool RELU>
__global__ __launch_bounds__(256, 2)
void sgemm_kernel(const float* __restrict__ A, const float* __restrict__ B,
                  const float* __restrict__ bias, float* __restrict__ C,
                  int M, int N, int K) {
    constexpr int BM = 128, BN = 64, BK = 8, TM = 8, TN = 4;
    __shared__ float As[BK][BM];
    __shared__ float Bs[BK][BN];

    const int tid = threadIdx.x;
    const int blockRow = blockIdx.y * BM;
    const int blockCol = blockIdx.x * BN;

    // thread micro-tile
    const int tCol = (tid % (BN / TN)) * TN;   // 16 groups of 4 cols
    const int tRow = (tid / (BN / TN)) * TM;   // 16 groups of 8 rows

    // A tile load map: BM*BK/4 = 256 float4, one per thread; coalesced (32B per row)
    const int aRow = tid >> 1;                 // [0,128)
    const int aCol = (tid & 1) * 4;            // 0 or 4
    // B tile load map: BK*BN/4 = 128 float4, tid<128; coalesced along N
    const int bRow = tid >> 4;                 // [0,16) -> only [0,8) valid
    const int bCol = (tid & 15) * 4;

    const float* Ap = A + (long)(blockRow + aRow) * K + aCol;
    const float* Bp = B + (long)bRow * N + blockCol + bCol;

    unsigned long long acc[TM / 2][TN];
#pragma unroll
    for (int i = 0; i < TM / 2; i++)
#pragma unroll
        for (int j = 0; j < TN; j++) acc[i][j] = 0ULL;

    float4 av = *(const float4*)(Ap);
    float4 bv = (tid < 128) ? *(const float4*)(Bp) : make_float4(0.f, 0.f, 0.f, 0.f);

    for (int k0 = 0; k0 < K; k0 += BK) {
        // stage regs -> smem
        As[aCol + 0][aRow] = av.x;
        As[aCol + 1][aRow] = av.y;
        As[aCol + 2][aRow] = av.z;
        As[aCol + 3][aRow] = av.w;
        if (tid < 128) *(float4*)&Bs[bRow][bCol] = bv;
        __syncthreads();

        // prefetch next tile
        if (k0 + BK < K) {
            av = *(const float4*)(Ap + k0 + BK);
            if (tid < 128) bv = *(const float4*)(Bp + (long)(k0 + BK) * N);
        }

#pragma unroll
        for (int k = 0; k < BK; k++) {
            const unsigned long long* ap =
                (const unsigned long long*)&As[k][tRow];   // 4 M-pairs
            unsigned long long a2[TM / 2];
#pragma unroll
            for (int i = 0; i < TM / 2; i++) a2[i] = ap[i];

            const float4 brv = *(const float4*)&Bs[k][tCol];
            unsigned long long b2[TN];
            b2[0] = pack2(brv.x, brv.x);
            b2[1] = pack2(brv.y, brv.y);
            b2[2] = pack2(brv.z, brv.z);
            b2[3] = pack2(brv.w, brv.w);

#pragma unroll
            for (int i = 0; i < TM / 2; i++)
#pragma unroll
                for (int j = 0; j < TN; j++)
                    acc[i][j] = ffma2(a2[i], b2[j], acc[i][j]);
        }
        __syncthreads();
    }

    // epilogue
    float bvals[TN];
#pragma unroll
    for (int j = 0; j < TN; j++) bvals[j] = BIAS ? bias[blockCol + tCol + j] : 0.f;

#pragma unroll
    for (int i = 0; i < TM / 2; i++) {
        float lo[TN], hi[TN];
#pragma unroll
        for (int j = 0; j < TN; j++) {
            unpack2(acc[i][j], lo[j], hi[j]);
            if (BIAS) { lo[j] += bvals[j]; hi[j] += bvals[j]; }
            if (RELU) { lo[j] = fmaxf(lo[j], 0.f); hi[j] = fmaxf(hi[j], 0.f); }
        }
        const int r0 = blockRow + tRow + 2 * i;
        float4* c0 = (float4*)&C[(long)r0 * N + blockCol + tCol];
        float4* c1 = (float4*)&C[(long)(r0 + 1) * N + blockCol + tCol];
        *c0 = make_float4(lo[0], lo[1], lo[2], lo[3]);
        *c1 = make_float4(hi[0], hi[1], hi[2], hi[3]);
    }
}

// ---------------- Q head: q[row] = dot(z[row,:128], Wq2) + bq2 ----------------
__global__ void qhead_kernel(const float* __restrict__ z,
                             const float* __restrict__ wq2,
                             const float* __restrict__ bq2,
                             float* __restrict__ out) {
    const int row  = blockIdx.x * 8 + (threadIdx.x >> 5);
    const int lane = threadIdx.x & 31;
    const float* zr = z + row * 128;
    float s = 0.f;
#pragma unroll
    for (int c = lane; c < 128; c += 32) s += zr[c] * wq2[c];
#pragma unroll
    for (int o = 16; o > 0; o >>= 1) s += __shfl_xor_sync(0xffffffffu, s, o);
    if (lane == 0) out[row] = s + bq2[0];
}

// ---------------- launch ----------------
static float* sym_addr(const void* sym) {
    void* p = nullptr;
    cudaGetSymbolAddress(&p, sym);
    return (float*)p;
}

extern "C" void kernel_launch(void* const* d_in, const int* in_sizes, int n_in,
                              void* d_out, int out_size) {
    const float* state = (const float*)d_in[0];
    const float* adj   = (const float*)d_in[1];
    const float* gamma = (const float*)d_in[2];
    const float* beta  = (const float*)d_in[3];
    const float* W1    = (const float*)d_in[4];
    const float* b1    = (const float*)d_in[5];
    const float* W2    = (const float*)d_in[6];
    const float* b2    = (const float*)d_in[7];
    const float* Wq1   = (const float*)d_in[8];
    const float* bq1   = (const float*)d_in[9];
    const float* Wq2   = (const float*)d_in[10];
    const float* bq2   = (const float*)d_in[11];
    float* out = (float*)d_out;

    float* ss = sym_addr(g_ss);
    float* xn = sym_addr(g_xn);
    float* y  = sym_addr(g_y);
    float* h  = sym_addr(g_h);
    float* zz = sym_addr(g_z);

    const int N = 8192;

    // BatchNorm (training-mode batch stats)
    bn_stats_kernel<<<128, 256>>>(state, gamma, beta, ss);
    bn_apply_kernel<<<(N * 128) / 256, 256>>>(state, ss, xn);

    // Y1 = xn @ W1                       [8192,128]x[128,256]
    sgemm_kernel<false, false><<<dim3(256 / 64, N / 128), 256>>>(xn, W1, nullptr, y, N, 256, 128);
    // H1 = relu(A @ Y1 + b1)             [8192,8192]x[8192,256]
    sgemm_kernel<true, true><<<dim3(256 / 64, N / 128), 256>>>(adj, y, b1, h, N, 256, N);
    // Y2 = H1 @ W2                       [8192,256]x[256,256]
    sgemm_kernel<false, false><<<dim3(256 / 64, N / 128), 256>>>(h, W2, nullptr, y, N, 256, 256);
    // H2 = relu(A @ Y2 + b2)
    sgemm_kernel<true, true><<<dim3(256 / 64, N / 128), 256>>>(adj, y, b2, h, N, 256, N);
    // Z = relu(H2 @ Wq1 + bq1)           [8192,256]x[256,128]
    sgemm_kernel<true, true><<<dim3(128 / 64, N / 128), 256>>>(h, Wq1, bq1, zz, N, 128, 256);
    // q = Z @ Wq2 + bq2                  [8192,128]x[128,1]
    qhead_kernel<<<N / 8, 256>>>(zz, Wq2, bq2, out);
}

// round 4
// speedup vs baseline: 4.6147x; 4.6147x over previous
#include <cuda_runtime.h>
#include <cuda_bf16.h>
#include <cstdint>

// ---------------- scratch (__device__ globals; no runtime alloc) ----------------
__device__ float g_ss[256];             // BN scale/shift
__device__ float g_xn[8192 * 128];      // normalized state
__device__ float g_y [8192 * 256];      // small-GEMM output (row-major, tf32-rounded)
__device__ float g_h [8192 * 256];      // big-GEMM output
__device__ float g_z [8192 * 128];      // relu(h@Wq1+bq1)
__device__ float g_at[8192UL * 8192UL]; // tf32-rounded adjacency (256MB)

// ---------------- helpers ----------------
__device__ __forceinline__ uint32_t smem_u32(const void* p) {
    uint32_t a;
    asm("{ .reg .u64 t; cvta.to.shared.u64 t, %1; cvt.u32.u64 %0, t; }" : "=r"(a) : "l"(p));
    return a;
}
__device__ __forceinline__ float tf32_rn(float x) {
    uint32_t u;
    asm("cvt.rna.tf32.f32 %0, %1;" : "=r"(u) : "r"(__float_as_uint(x)));
    return __uint_as_float(u);
}
__device__ __forceinline__ void cp_async16(uint32_t dst, const void* src) {
    asm volatile("cp.async.cg.shared.global [%0], [%1], 16;" :: "r"(dst), "l"(src) : "memory");
}
#define CP_COMMIT() asm volatile("cp.async.commit_group;" ::: "memory")
#define CP_WAIT1()  asm volatile("cp.async.wait_group 1;" ::: "memory")

// ---------------- big tensor-core GEMM ----------------
// C[8192,256] = relu(A[8192,K] @ B[K,256] + bias), A tf32-pre-rounded, B tf32-pre-rounded.
// BM=128, BN=128, BK=32, 3-stage cp.async pipeline, 256 threads, warp tile 64x32.
static constexpr int GN = 256;
static constexpr int BM = 128, BNt = 128, BK = 32, STAGES = 3;
static constexpr int AP = 36;                  // A smem row stride (words), conflict-free frags
static constexpr int BP = 136;                 // B smem row stride (words)
static constexpr int A_WORDS = BM * AP;        // 4608
static constexpr int B_WORDS = BK * BP;        // 4352
static constexpr int STAGE_WORDS = A_WORDS + B_WORDS;        // 8960
static constexpr int BIG_SMEM = STAGES * STAGE_WORDS * 4;    // 107520 B

__device__ __forceinline__ void load_chunk(uint32_t sbase, int s,
                                           const float* __restrict__ A,
                                           const float* __restrict__ B,
                                           int blockRow, int blockCol, int kcol, int K,
                                           int tid) {
    const uint32_t sa = sbase + (uint32_t)s * STAGE_WORDS * 4;
#pragma unroll
    for (int i = 0; i < 4; i++) {              // A: 128x32 floats = 1024 float4
        int idx = tid + 256 * i;
        int row = idx >> 3, c4 = idx & 7;
        cp_async16(sa + (row * AP + c4 * 4) * 4,
                   A + (size_t)(blockRow + row) * K + kcol + c4 * 4);
    }
#pragma unroll
    for (int i = 0; i < 4; i++) {              // B: 32x128 floats = 1024 float4
        int idx = tid + 256 * i;
        int row = idx >> 5, c4 = idx & 31;
        cp_async16(sa + (A_WORDS + row * BP + c4 * 4) * 4,
                   B + (size_t)(kcol + row) * GN + blockCol + c4 * 4);
    }
    CP_COMMIT();
}

__global__ __launch_bounds__(256, 1)
void mma_gemm_kernel(const float* __restrict__ A, const float* __restrict__ B,
                     const float* __restrict__ bias, float* __restrict__ C, int K) {
    extern __shared__ float sm[];
    const uint32_t sbase = smem_u32(sm);
    const int tid = threadIdx.x, lane = tid & 31, wid = tid >> 5;
    const int wm = (wid & 1) * 64, wn = (wid >> 1) * 32;
    const int blockRow = blockIdx.y * BM, blockCol = blockIdx.x * BNt;
    const int g = lane >> 2, tg = lane & 3;

    float acc[4][4][4];
#pragma unroll
    for (int mi = 0; mi < 4; mi++)
#pragma unroll
        for (int ni = 0; ni < 4; ni++)
#pragma unroll
            for (int r = 0; r < 4; r++) acc[mi][ni][r] = 0.f;

    const int NCHUNK = K / BK;
    load_chunk(sbase, 0, A, B, blockRow, blockCol, 0, K, tid);
    load_chunk(sbase, 1, A, B, blockRow, blockCol, BK, K, tid);

    for (int c = 0; c < NCHUNK; c++) {
        CP_WAIT1();
        __syncthreads();
        if (c + 2 < NCHUNK)
            load_chunk(sbase, (c + 2) % STAGES, A, B, blockRow, blockCol, (c + 2) * BK, K, tid);
        else
            CP_COMMIT();   // empty group keeps wait_group(1) accounting uniform

        const float* As = sm + (c % STAGES) * STAGE_WORDS;
        const float* Bs = As + A_WORDS;
#pragma unroll
        for (int ks = 0; ks < 4; ks++) {
            const int kc = ks * 8;
            uint32_t af[4][4], bf[4][2];
#pragma unroll
            for (int mi = 0; mi < 4; mi++) {
                int r0 = wm + mi * 16 + g;
                af[mi][0] = __float_as_uint(As[r0 * AP + kc + tg]);
                af[mi][1] = __float_as_uint(As[(r0 + 8) * AP + kc + tg]);
                af[mi][2] = __float_as_uint(As[r0 * AP + kc + tg + 4]);
                af[mi][3] = __float_as_uint(As[(r0 + 8) * AP + kc + tg + 4]);
            }
#pragma unroll
            for (int ni = 0; ni < 4; ni++) {
                int c0 = wn + ni * 8 + g;
                bf[ni][0] = __float_as_uint(Bs[(kc + tg) * BP + c0]);
                bf[ni][1] = __float_as_uint(Bs[(kc + 4 + tg) * BP + c0]);
            }
#pragma unroll
            for (int mi = 0; mi < 4; mi++)
#pragma unroll
                for (int ni = 0; ni < 4; ni++)
                    asm volatile(
                        "mma.sync.aligned.m16n8k8.row.col.f32.tf32.tf32.f32 "
                        "{%0,%1,%2,%3},{%4,%5,%6,%7},{%8,%9},{%0,%1,%2,%3};"
                        : "+f"(acc[mi][ni][0]), "+f"(acc[mi][ni][1]),
                          "+f"(acc[mi][ni][2]), "+f"(acc[mi][ni][3])
                        : "r"(af[mi][0]), "r"(af[mi][1]), "r"(af[mi][2]), "r"(af[mi][3]),
                          "r"(bf[ni][0]), "r"(bf[ni][1]));
        }
    }

    // epilogue: bias + relu fused
#pragma unroll
    for (int mi = 0; mi < 4; mi++) {
        const int r0 = blockRow + wm + mi * 16 + g;
#pragma unroll
        for (int ni = 0; ni < 4; ni++) {
            const int col = blockCol + wn + ni * 8 + 2 * tg;
            const float b0 = bias[col], b1 = bias[col + 1];
            float2 v0 = make_float2(fmaxf(acc[mi][ni][0] + b0, 0.f),
                                    fmaxf(acc[mi][ni][1] + b1, 0.f));
            float2 v1 = make_float2(fmaxf(acc[mi][ni][2] + b0, 0.f),
                                    fmaxf(acc[mi][ni][3] + b1, 0.f));
            *(float2*)&C[(size_t)r0 * GN + col] = v0;
            *(float2*)&C[(size_t)(r0 + 8) * GN + col] = v1;
        }
    }
}

// ---------------- tf32 RNA round of A ----------------
__global__ void round_a_kernel(const float* __restrict__ in, float* __restrict__ out) {
    const size_t n4 = 8192UL * 8192UL / 4;
    size_t i = (size_t)blockIdx.x * blockDim.x + threadIdx.x;
    const size_t stride = (size_t)gridDim.x * blockDim.x;
    for (; i < n4; i += stride) {
        float4 v = ((const float4*)in)[i];
        v.x = tf32_rn(v.x); v.y = tf32_rn(v.y); v.z = tf32_rn(v.z); v.w = tf32_rn(v.w);
        ((float4*)out)[i] = v;
    }
}

// ---------------- BatchNorm ----------------
__global__ void bn_stats_kernel(const float* __restrict__ state, const float* __restrict__ gamma,
                                const float* __restrict__ beta, float* __restrict__ ss) {
    const int j = blockIdx.x;
    float s = 0.f, s2 = 0.f;
    for (int i = threadIdx.x; i < 8192; i += 256) {
        float v = state[i * 128 + j];
        s += v; s2 += v * v;
    }
    __shared__ float sh[512];
    sh[threadIdx.x] = s; sh[256 + threadIdx.x] = s2;
    __syncthreads();
    for (int o = 128; o > 0; o >>= 1) {
        if (threadIdx.x < o) {
            sh[threadIdx.x] += sh[threadIdx.x + o];
            sh[256 + threadIdx.x] += sh[256 + threadIdx.x + o];
        }
        __syncthreads();
    }
    if (threadIdx.x == 0) {
        float mean = sh[0] * (1.f / 8192.f);
        float var = sh[256] * (1.f / 8192.f) - mean * mean;
        float sc = gamma[j] * rsqrtf(var + 1e-5f);
        ss[j] = sc;
        ss[128 + j] = beta[j] - mean * sc;
    }
}
__global__ void bn_apply_kernel(const float* __restrict__ state, const float* __restrict__ ss,
                                float* __restrict__ xn) {
    int idx = blockIdx.x * blockDim.x + threadIdx.x;
    if (idx < 8192 * 128) {
        int j = idx & 127;
        xn[idx] = fmaf(state[idx], ss[j], ss[128 + j]);
    }
}

// ---------------- scalar SGEMM (small GEMMs) ----------------
template <bool BIAS, bool RELU, bool ROUND>
__global__ __launch_bounds__(256, 2)
void sgemm_kernel(const float* __restrict__ A, const float* __restrict__ B,
                  const float* __restrict__ bias, float* __restrict__ C,
                  int M, int N, int K) {
    constexpr int SBM = 128, SBN = 64, SBK = 8, TM = 8, TN = 4;
    __shared__ float As[SBK][SBM];
    __shared__ float Bs[SBK][SBN];
    const int tid = threadIdx.x;
    const int blockRow = blockIdx.y * SBM;
    const int blockCol = blockIdx.x * SBN;
    const int tCol = (tid % (SBN / TN)) * TN;
    const int tRow = (tid / (SBN / TN)) * TM;
    const int aRow = tid >> 1, aCol = (tid & 1) * 4;
    const int bRow = tid >> 4, bCol = (tid & 15) * 4;
    const float* Ap = A + (size_t)(blockRow + aRow) * K + aCol;
    const float* Bp = B + (size_t)bRow * N + blockCol + bCol;

    float acc[TM][TN];
#pragma unroll
    for (int i = 0; i < TM; i++)
#pragma unroll
        for (int j = 0; j < TN; j++) acc[i][j] = 0.f;

    float4 av = *(const float4*)(Ap);
    float4 bv = (tid < 128) ? *(const float4*)(Bp) : make_float4(0.f, 0.f, 0.f, 0.f);

    for (int k0 = 0; k0 < K; k0 += SBK) {
        As[aCol + 0][aRow] = av.x; As[aCol + 1][aRow] = av.y;
        As[aCol + 2][aRow] = av.z; As[aCol + 3][aRow] = av.w;
        if (tid < 128) *(float4*)&Bs[bRow][bCol] = bv;
        __syncthreads();
        if (k0 + SBK < K) {
            av = *(const float4*)(Ap + k0 + SBK);
            if (tid < 128) bv = *(const float4*)(Bp + (size_t)(k0 + SBK) * N);
        }
#pragma unroll
        for (int k = 0; k < SBK; k++) {
            float ar[TM];
#pragma unroll
            for (int i = 0; i < TM; i++) ar[i] = As[k][tRow + i];
            const float4 brv = *(const float4*)&Bs[k][tCol];
            const float br[TN] = {brv.x, brv.y, brv.z, brv.w};
#pragma unroll
            for (int i = 0; i < TM; i++)
#pragma unroll
                for (int j = 0; j < TN; j++) acc[i][j] = fmaf(ar[i], br[j], acc[i][j]);
        }
        __syncthreads();
    }
#pragma unroll
    for (int i = 0; i < TM; i++) {
        float v[TN];
#pragma unroll
        for (int j = 0; j < TN; j++) {
            v[j] = acc[i][j];
            if (BIAS) v[j] += bias[blockCol + tCol + j];
            if (RELU) v[j] = fmaxf(v[j], 0.f);
            if (ROUND) v[j] = tf32_rn(v[j]);
        }
        *(float4*)&C[(size_t)(blockRow + tRow + i) * N + blockCol + tCol] =
            make_float4(v[0], v[1], v[2], v[3]);
    }
}

// ---------------- Q head ----------------
__global__ void qhead_kernel(const float* __restrict__ z, const float* __restrict__ wq2,
                             const float* __restrict__ bq2, float* __restrict__ out) {
    const int row = blockIdx.x * 8 + (threadIdx.x >> 5);
    const int lane = threadIdx.x & 31;
    const float* zr = z + row * 128;
    float s = 0.f;
#pragma unroll
    for (int c = lane; c < 128; c += 32) s += zr[c] * wq2[c];
#pragma unroll
    for (int o = 16; o > 0; o >>= 1) s += __shfl_xor_sync(0xffffffffu, s, o);
    if (lane == 0) out[row] = s + bq2[0];
}

// ---------------- launch ----------------
static float* sym_addr(const void* sym) {
    void* p = nullptr;
    cudaGetSymbolAddress(&p, sym);
    return (float*)p;
}

extern "C" void kernel_launch(void* const* d_in, const int* in_sizes, int n_in,
                              void* d_out, int out_size) {
    const float* state = (const float*)d_in[0];
    const float* adj   = (const float*)d_in[1];
    const float* gamma = (const float*)d_in[2];
    const float* beta  = (const float*)d_in[3];
    const float* W1    = (const float*)d_in[4];
    const float* b1    = (const float*)d_in[5];
    const float* W2    = (const float*)d_in[6];
    const float* b2    = (const float*)d_in[7];
    const float* Wq1   = (const float*)d_in[8];
    const float* bq1   = (const float*)d_in[9];
    const float* Wq2   = (const float*)d_in[10];
    const float* bq2   = (const float*)d_in[11];
    float* out = (float*)d_out;

    float* ss = sym_addr(g_ss);
    float* xn = sym_addr(g_xn);
    float* y  = sym_addr(g_y);
    float* h  = sym_addr(g_h);
    float* zz = sym_addr(g_z);
    float* at = sym_addr(g_at);

    cudaFuncSetAttribute(mma_gemm_kernel, cudaFuncAttributeMaxDynamicSharedMemorySize, BIG_SMEM);

    const int N = 8192;

    bn_stats_kernel<<<128, 256>>>(state, gamma, beta, ss);
    bn_apply_kernel<<<(N * 128) / 256, 256>>>(state, ss, xn);
    round_a_kernel<<<2048, 256>>>(adj, at);

    // Y1 = round_tf32(xn @ W1)
    sgemm_kernel<false, false, true><<<dim3(256 / 64, N / 128), 256>>>(xn, W1, nullptr, y, N, 256, 128);
    // H1 = relu(A @ Y1 + b1)  (tensor cores, tf32)
    mma_gemm_kernel<<<dim3(GN / BNt, N / BM), 256, BIG_SMEM>>>(at, y, b1, h, N);
    // Y2 = round_tf32(H1 @ W2)
    sgemm_kernel<false, false, true><<<dim3(256 / 64, N / 128), 256>>>(h, W2, nullptr, y, N, 256, 256);
    // H2 = relu(A @ Y2 + b2)
    mma_gemm_kernel<<<dim3(GN / BNt, N / BM), 256, BIG_SMEM>>>(at, y, b2, h, N);
    // Z = relu(H2 @ Wq1 + bq1)  (fp32)
    sgemm_kernel<true, true, false><<<dim3(128 / 64, N / 128), 256>>>(h, Wq1, bq1, zz, N, 128, 256);
    // q = Z @ Wq2 + bq2
    qhead_kernel<<<N / 8, 256>>>(zz, Wq2, bq2, out);
}